// round 1
// baseline (speedup 1.0000x reference)
#include <cuda_runtime.h>
#include <math.h>

#define BLC 4
#define LEN 1024
#define HN 16
#define DH 64
#define EMB 1024
#define BL (BLC*LEN)          // 4096 rows total
#define MINV (-1.7014117e38f) // float32 min / 2

// Scratch (allocation-free rule: __device__ globals)
__device__ float g_Q[BL*EMB];
__device__ float g_K[BL*EMB];
__device__ float g_V[BL*EMB];
__device__ float g_Val[BL*EMB];
__device__ float g_Y[BL*EMB];

// ---------------------------------------------------------------------------
// Kernel 1: QKV projections.  C[4096,1024] = X[4096,1024] @ Wcat + b
// Wcat column c (= h*64+d) row i lives at W[h*65536 + i*64 + d].
// grid: (16 nTiles, 64 mTiles, 3 {q,k,v}), block 16x16, 4x4 micro-tile.
// ---------------------------------------------------------------------------
__global__ __launch_bounds__(256) void qkv_kernel(
    const float* __restrict__ x,
    const float* __restrict__ Wq, const float* __restrict__ bq,
    const float* __restrict__ Wk, const float* __restrict__ bk,
    const float* __restrict__ Wv, const float* __restrict__ bv)
{
    const float* W; const float* bias; float* out;
    int z = blockIdx.z;
    if (z == 0)      { W = Wq; bias = bq; out = g_Q; }
    else if (z == 1) { W = Wk; bias = bk; out = g_K; }
    else             { W = Wv; bias = bv; out = g_V; }

    __shared__ float As[16][64];
    __shared__ float Bs[16][64];

    int tx = threadIdx.x, ty = threadIdx.y;
    int tid = ty * 16 + tx;
    int rowbase = blockIdx.y * 64;
    int head    = blockIdx.x;           // N-tile == head (64 cols each)

    float acc[4][4] = {};

    for (int kb = 0; kb < EMB; kb += 16) {
        #pragma unroll
        for (int e = 0; e < 4; e++) {
            int idx = tid + e * 256;
            int r = idx >> 4, c = idx & 15;
            As[c][r] = x[(size_t)(rowbase + r) * EMB + kb + c];
        }
        #pragma unroll
        for (int e = 0; e < 4; e++) {
            int idx = tid + e * 256;
            int ki = idx >> 6, cl = idx & 63;
            Bs[ki][cl] = W[(size_t)head * (EMB * DH) + (size_t)(kb + ki) * DH + cl];
        }
        __syncthreads();
        #pragma unroll
        for (int kk = 0; kk < 16; kk++) {
            float a[4], b[4];
            #pragma unroll
            for (int i = 0; i < 4; i++) a[i] = As[kk][ty * 4 + i];
            #pragma unroll
            for (int j = 0; j < 4; j++) b[j] = Bs[kk][tx * 4 + j];
            #pragma unroll
            for (int i = 0; i < 4; i++)
                #pragma unroll
                for (int j = 0; j < 4; j++)
                    acc[i][j] += a[i] * b[j];
        }
        __syncthreads();
    }

    #pragma unroll
    for (int i = 0; i < 4; i++) {
        int r = rowbase + ty * 4 + i;
        #pragma unroll
        for (int j = 0; j < 4; j++) {
            int c = head * 64 + tx * 4 + j;
            out[(size_t)r * EMB + c] = acc[i][j] + bias[c];
        }
    }
}

// ---------------------------------------------------------------------------
// Kernel 2: fused attention for one (b,h, 32-row tile).
// Computes S = QK^T*scale (masked), softmax (writes atten to d_out), then P@V
// into the concat layout g_Val[4096,1024].
// grid: (64 bh, 32 rowTiles), block 16x16, dynamic smem ~157 KB.
// ---------------------------------------------------------------------------
#define AROWS 32
#define SQ_STRIDE 65
#define SK_STRIDE 65
#define SS_STRIDE 1025

__global__ __launch_bounds__(256) void attn_kernel(
    const int* __restrict__ mask, float* __restrict__ atten_out)
{
    extern __shared__ float sm[];
    float* sQ  = sm;                                 // 32*65   = 2080
    float* sK  = sQ + AROWS * SQ_STRIDE;             // 64*65   = 4160
    float* sS  = sK + 64 * SK_STRIDE;                // 32*1025 = 32800
    float* sMk = sS + AROWS * SS_STRIDE;             // 1024

    int bh   = blockIdx.x;
    int tile = blockIdx.y;
    int b = bh >> 4, h = bh & 15;
    int l0 = tile * AROWS;
    int tx = threadIdx.x, ty = threadIdx.y;
    int tid = ty * 16 + tx;

    // Load Q tile [32 x 64]
    const float* Qbase = g_Q + ((size_t)(b * LEN + l0)) * EMB + h * DH;
    #pragma unroll
    for (int e = 0; e < 8; e++) {
        int idx = tid + e * 256;
        int r = idx >> 6, d = idx & 63;
        sQ[r * SQ_STRIDE + d] = Qbase[(size_t)r * EMB + d];
    }
    // Mask row for this batch
    #pragma unroll
    for (int e = 0; e < 4; e++) {
        int idx = tid + e * 256;
        sMk[idx] = (float)mask[b * LEN + idx];
    }
    __syncthreads();

    const float scale = 0.125f;  // 1/sqrt(64)

    // ---- S = Q @ K^T, masked, scaled ----
    for (int kt = 0; kt < 16; kt++) {
        const float* Kbase = g_K + ((size_t)(b * LEN + kt * 64)) * EMB + h * DH;
        #pragma unroll
        for (int e = 0; e < 16; e++) {
            int idx = tid + e * 256;
            int r = idx >> 6, d = idx & 63;
            sK[r * SK_STRIDE + d] = Kbase[(size_t)r * EMB + d];
        }
        __syncthreads();

        float acc0[4] = {}, acc1[4] = {};
        #pragma unroll 16
        for (int d = 0; d < DH; d++) {
            float q0 = sQ[(2 * ty)     * SQ_STRIDE + d];
            float q1 = sQ[(2 * ty + 1) * SQ_STRIDE + d];
            #pragma unroll
            for (int jj = 0; jj < 4; jj++) {
                float kv = sK[(tx + 16 * jj) * SK_STRIDE + d];
                acc0[jj] += q0 * kv;
                acc1[jj] += q1 * kv;
            }
        }
        #pragma unroll
        for (int jj = 0; jj < 4; jj++) {
            int j = tx + 16 * jj;
            int m = kt * 64 + j;
            float keep = sMk[m];
            float s0 = acc0[jj] * scale;
            float s1 = acc1[jj] * scale;
            s0 = (keep == 0.0f) ? MINV : s0;
            s1 = (keep == 0.0f) ? MINV : s1;
            sS[(2 * ty)     * SS_STRIDE + m] = s0;
            sS[(2 * ty + 1) * SS_STRIDE + m] = s1;
        }
        __syncthreads();
    }

    // ---- softmax per row; write atten to gmem, probs back into sS ----
    int warp = tid >> 5, lane = tid & 31;
    for (int r = warp; r < AROWS; r += 8) {
        float* row = sS + r * SS_STRIDE;
        float mx = -3.4e38f;
        #pragma unroll
        for (int c = lane; c < 1024; c += 32) mx = fmaxf(mx, row[c]);
        #pragma unroll
        for (int o = 16; o; o >>= 1) mx = fmaxf(mx, __shfl_xor_sync(0xffffffffu, mx, o));
        float sum = 0.0f;
        #pragma unroll
        for (int c = lane; c < 1024; c += 32) {
            float e = __expf(row[c] - mx);
            row[c] = e;
            sum += e;
        }
        #pragma unroll
        for (int o = 16; o; o >>= 1) sum += __shfl_xor_sync(0xffffffffu, sum, o);
        float inv = 1.0f / sum;
        float* arow = atten_out + ((size_t)(b * HN + h) * LEN + (l0 + r)) * LEN;
        #pragma unroll
        for (int c = lane; c < 1024; c += 32) {
            float p = row[c] * inv;
            row[c] = p;
            arow[c] = p;
        }
    }
    __syncthreads();

    // ---- P @ V -> g_Val concat layout ----
    float vacc0[4] = {}, vacc1[4] = {};
    for (int mt = 0; mt < 16; mt++) {
        const float* Vbase = g_V + ((size_t)(b * LEN + mt * 64)) * EMB + h * DH;
        #pragma unroll
        for (int e = 0; e < 16; e++) {
            int idx = tid + e * 256;
            int r = idx >> 6, d = idx & 63;
            sK[r * SK_STRIDE + d] = Vbase[(size_t)r * EMB + d];
        }
        __syncthreads();
        #pragma unroll 16
        for (int mm = 0; mm < 64; mm++) {
            float p0 = sS[(2 * ty)     * SS_STRIDE + mt * 64 + mm];
            float p1 = sS[(2 * ty + 1) * SS_STRIDE + mt * 64 + mm];
            #pragma unroll
            for (int dd = 0; dd < 4; dd++) {
                float vv = sK[mm * SK_STRIDE + tx + 16 * dd];
                vacc0[dd] += p0 * vv;
                vacc1[dd] += p1 * vv;
            }
        }
        __syncthreads();
    }
    #pragma unroll
    for (int dd = 0; dd < 4; dd++) {
        int d = tx + 16 * dd;
        size_t r0 = (size_t)(b * LEN + l0 + 2 * ty) * EMB + h * DH + d;
        g_Val[r0]       = vacc0[dd];
        g_Val[r0 + EMB] = vacc1[dd];
    }
}

// ---------------------------------------------------------------------------
// Kernel 3: out projection + bias + residual.  Y = Val @ Wo^T + bo + x
// ---------------------------------------------------------------------------
__global__ __launch_bounds__(256) void proj_kernel(
    const float* __restrict__ Wo, const float* __restrict__ bo,
    const float* __restrict__ x)
{
    __shared__ float As[16][64];
    __shared__ float Bs[16][65];

    int tx = threadIdx.x, ty = threadIdx.y;
    int tid = ty * 16 + tx;
    int rowbase = blockIdx.y * 64;
    int nbase   = blockIdx.x * 64;

    float acc[4][4] = {};

    for (int kb = 0; kb < EMB; kb += 16) {
        #pragma unroll
        for (int e = 0; e < 4; e++) {
            int idx = tid + e * 256;
            int r = idx >> 4, c = idx & 15;
            As[c][r] = g_Val[(size_t)(rowbase + r) * EMB + kb + c];
        }
        #pragma unroll
        for (int e = 0; e < 4; e++) {
            int idx = tid + e * 256;
            int ol = idx >> 4, ki = idx & 15;
            Bs[ki][ol] = Wo[(size_t)(nbase + ol) * EMB + kb + ki];
        }
        __syncthreads();
        #pragma unroll
        for (int kk = 0; kk < 16; kk++) {
            float a[4], bb[4];
            #pragma unroll
            for (int i = 0; i < 4; i++) a[i]  = As[kk][ty * 4 + i];
            #pragma unroll
            for (int j = 0; j < 4; j++) bb[j] = Bs[kk][tx * 4 + j];
            #pragma unroll
            for (int i = 0; i < 4; i++)
                #pragma unroll
                for (int j = 0; j < 4; j++)
                    acc[i][j] += a[i] * bb[j];
        }
        __syncthreads();
    }

    #pragma unroll
    for (int i = 0; i < 4; i++) {
        int r = rowbase + ty * 4 + i;
        #pragma unroll
        for (int j = 0; j < 4; j++) {
            int c = nbase + tx * 4 + j;
            g_Y[(size_t)r * EMB + c] = acc[i][j] + bo[c] + x[(size_t)r * EMB + c];
        }
    }
}

// ---------------------------------------------------------------------------
// Kernel 4: row LayerNorm -> d_out[:4M]
// ---------------------------------------------------------------------------
__global__ __launch_bounds__(256) void ln_kernel(
    const float* __restrict__ gamma, const float* __restrict__ beta,
    float* __restrict__ out)
{
    int r = blockIdx.x;
    const float* row = g_Y + (size_t)r * EMB;
    int tid = threadIdx.x;

    float v[4];
    float s = 0.0f, s2 = 0.0f;
    #pragma unroll
    for (int e = 0; e < 4; e++) {
        v[e] = row[tid + e * 256];
        s  += v[e];
        s2 += v[e] * v[e];
    }
    __shared__ float rs[8], rs2[8];
    #pragma unroll
    for (int o = 16; o; o >>= 1) {
        s  += __shfl_xor_sync(0xffffffffu, s,  o);
        s2 += __shfl_xor_sync(0xffffffffu, s2, o);
    }
    if ((tid & 31) == 0) { rs[tid >> 5] = s; rs2[tid >> 5] = s2; }
    __syncthreads();
    if (tid < 32) {
        float a = (tid < 8) ? rs[tid]  : 0.0f;
        float c = (tid < 8) ? rs2[tid] : 0.0f;
        #pragma unroll
        for (int o = 4; o; o >>= 1) {
            a += __shfl_xor_sync(0xffffffffu, a, o);
            c += __shfl_xor_sync(0xffffffffu, c, o);
        }
        if (tid == 0) { rs[0] = a; rs2[0] = c; }
    }
    __syncthreads();
    float mu  = rs[0] * (1.0f / 1024.0f);
    float var = rs2[0] * (1.0f / 1024.0f) - mu * mu;
    float inv = rsqrtf(var + 1e-5f);
    #pragma unroll
    for (int e = 0; e < 4; e++) {
        int c = tid + e * 256;
        out[(size_t)r * EMB + c] = (v[e] - mu) * inv * gamma[c] + beta[c];
    }
}

// ---------------------------------------------------------------------------
extern "C" void kernel_launch(void* const* d_in, const int* in_sizes, int n_in,
                              void* d_out, int out_size)
{
    const float* x     = (const float*)d_in[0];
    const int*   mask  = (const int*)  d_in[1];
    const float* Wq    = (const float*)d_in[2];
    const float* bq    = (const float*)d_in[3];
    const float* Wk    = (const float*)d_in[4];
    const float* bk    = (const float*)d_in[5];
    const float* Wv    = (const float*)d_in[6];
    const float* bv    = (const float*)d_in[7];
    const float* Wo    = (const float*)d_in[8];
    const float* bo    = (const float*)d_in[9];
    const float* gamma = (const float*)d_in[10];
    const float* beta  = (const float*)d_in[11];

    float* out   = (float*)d_out;                 // [4,1024,1024]
    float* atten = out + (size_t)BL * EMB;        // [4,16,1024,1024]

    const int ATTN_SMEM = (AROWS * SQ_STRIDE + 64 * SK_STRIDE +
                           AROWS * SS_STRIDE + 1024) * (int)sizeof(float);
    cudaFuncSetAttribute(attn_kernel,
                         cudaFuncAttributeMaxDynamicSharedMemorySize, ATTN_SMEM);

    qkv_kernel<<<dim3(16, 64, 3), dim3(16, 16)>>>(x, Wq, bq, Wk, bk, Wv, bv);
    attn_kernel<<<dim3(64, 32), dim3(16, 16), ATTN_SMEM>>>(mask, atten);
    proj_kernel<<<dim3(16, 64), dim3(16, 16)>>>(Wo, bo, x);
    ln_kernel<<<BL, 256>>>(gamma, beta, out);
}

// round 2
// speedup vs baseline: 1.6758x; 1.6758x over previous
#include <cuda_runtime.h>
#include <math.h>

#define BLC 4
#define LEN 1024
#define HN 16
#define DH 64
#define EMB 1024
#define BL (BLC*LEN)          // 4096 rows total
#define MINV (-1.7014117e38f) // float32 min / 2

// Scratch (allocation-free rule: __device__ globals)
__device__ float g_Q[BL*EMB];
__device__ float g_K[BL*EMB];
__device__ float g_V[BL*EMB];
__device__ float g_KT[BL*EMB];     // [b*16+h][64 d][1024 pos]
__device__ float g_WoT[EMB*EMB];   // Wo transposed: [k][n]
__device__ float g_Val[BL*EMB];
__device__ float g_Y[BL*EMB];

// ---------------------------------------------------------------------------
// tf32 helpers
// ---------------------------------------------------------------------------
__device__ __forceinline__ unsigned f2tf(float f) {
    unsigned u; asm("cvt.rna.tf32.f32 %0, %1;" : "=r"(u) : "f"(f)); return u;
}
__device__ __forceinline__ uint4 cvt4(float4 v) {
    uint4 u; u.x = f2tf(v.x); u.y = f2tf(v.y); u.z = f2tf(v.z); u.w = f2tf(v.w); return u;
}
// D = A(16x8,row) * B(8x8,col) + D, tf32 operands, fp32 accum
__device__ __forceinline__ void mma8(float* c,
                                     unsigned a0, unsigned a1, unsigned a2, unsigned a3,
                                     unsigned b0, unsigned b1) {
    asm volatile(
        "mma.sync.aligned.m16n8k8.row.col.f32.tf32.tf32.f32 "
        "{%0,%1,%2,%3}, {%4,%5,%6,%7}, {%8,%9}, {%0,%1,%2,%3};"
        : "+f"(c[0]), "+f"(c[1]), "+f"(c[2]), "+f"(c[3])
        : "r"(a0), "r"(a1), "r"(a2), "r"(a3), "r"(b0), "r"(b1));
}

// ---------------------------------------------------------------------------
// Kernel 1: QKV projections via tf32 mma.  C[4096,1024] = X @ Wcat + b
// Block tile 128(m) x 64(n == one head), kblock 32. 8 warps: 4(m) x 2(n),
// warp tile 32x32 = 2 m-frags x 4 n-frags of m16n8k8.
// ---------------------------------------------------------------------------
#define AS_STRIDE 36   // == 4 mod 32 -> conflict-free A-fragment fetch
#define BS_STRIDE 72   // == 8 mod 32 -> conflict-free B-fragment fetch

__global__ __launch_bounds__(256) void qkv_mma(
    const float* __restrict__ x,
    const float* __restrict__ Wq, const float* __restrict__ bq,
    const float* __restrict__ Wk, const float* __restrict__ bk,
    const float* __restrict__ Wv, const float* __restrict__ bv)
{
    const float* W; const float* bias; float* out;
    int z = blockIdx.z;
    if (z == 0)      { W = Wq; bias = bq; out = g_Q; }
    else if (z == 1) { W = Wk; bias = bk; out = g_K; }
    else             { W = Wv; bias = bv; out = g_V; }

    __shared__ unsigned As[128 * AS_STRIDE];
    __shared__ unsigned Bs[32 * BS_STRIDE];

    int tid = threadIdx.x;
    int wid = tid >> 5, lane = tid & 31;
    int wm = wid & 3, wn = wid >> 2;
    unsigned g = lane >> 2, t = lane & 3;

    int rowbase = blockIdx.y * 128;
    int head    = blockIdx.x;

    float acc[2][4][4] = {};

    for (int kb = 0; kb < EMB; kb += 32) {
        // Stage A: 128x32
        #pragma unroll
        for (int e = 0; e < 4; e++) {
            int r  = (tid >> 3) + 32 * e;
            int c4 = (tid & 7) * 4;
            float4 v = *(const float4*)&x[(size_t)(rowbase + r) * EMB + kb + c4];
            *(uint4*)&As[r * AS_STRIDE + c4] = cvt4(v);
        }
        // Stage B: 32x64, W row-major [k][64] within head
        #pragma unroll
        for (int e = 0; e < 2; e++) {
            int k  = (tid >> 4) + 16 * e;
            int c4 = (tid & 15) * 4;
            float4 v = *(const float4*)&W[(size_t)head * (EMB * DH) + (size_t)(kb + k) * DH + c4];
            *(uint4*)&Bs[k * BS_STRIDE + c4] = cvt4(v);
        }
        __syncthreads();

        #pragma unroll
        for (int ks = 0; ks < 4; ks++) {
            int k0 = ks * 8;
            unsigned a[2][4];
            #pragma unroll
            for (int mi = 0; mi < 2; mi++) {
                int base = (wm * 32 + mi * 16 + g) * AS_STRIDE + k0 + t;
                a[mi][0] = As[base];
                a[mi][1] = As[base + 8 * AS_STRIDE];
                a[mi][2] = As[base + 4];
                a[mi][3] = As[base + 8 * AS_STRIDE + 4];
            }
            unsigned b[4][2];
            #pragma unroll
            for (int ni = 0; ni < 4; ni++) {
                int cb = wn * 32 + ni * 8 + g;
                b[ni][0] = Bs[(k0 + t) * BS_STRIDE + cb];
                b[ni][1] = Bs[(k0 + t + 4) * BS_STRIDE + cb];
            }
            #pragma unroll
            for (int mi = 0; mi < 2; mi++)
                #pragma unroll
                for (int ni = 0; ni < 4; ni++)
                    mma8(acc[mi][ni], a[mi][0], a[mi][1], a[mi][2], a[mi][3],
                         b[ni][0], b[ni][1]);
        }
        __syncthreads();
    }

    // Epilogue: + bias
    #pragma unroll
    for (int mi = 0; mi < 2; mi++) {
        int row = rowbase + wm * 32 + mi * 16 + g;
        #pragma unroll
        for (int ni = 0; ni < 4; ni++) {
            int col = head * 64 + wn * 32 + ni * 8 + 2 * t;
            float b0 = bias[col], b1 = bias[col + 1];
            float2 v0 = make_float2(acc[mi][ni][0] + b0, acc[mi][ni][1] + b1);
            float2 v1 = make_float2(acc[mi][ni][2] + b0, acc[mi][ni][3] + b1);
            *(float2*)&out[(size_t)row * EMB + col]       = v0;
            *(float2*)&out[(size_t)(row + 8) * EMB + col] = v1;
        }
    }
}

// ---------------------------------------------------------------------------
// Transposes: K -> K^T per (b,h);  Wo -> Wo^T
// ---------------------------------------------------------------------------
__global__ void transpose_k() {
    __shared__ float tl[32][33];
    int bh = blockIdx.z;
    int b = bh >> 4, h = bh & 15;
    int p0 = blockIdx.x * 32, d0 = blockIdx.y * 32;
    int tx = threadIdx.x, ty = threadIdx.y;
    #pragma unroll
    for (int j = 0; j < 4; j++)
        tl[ty + 8 * j][tx] =
            g_K[(size_t)(b * LEN + p0 + ty + 8 * j) * EMB + h * DH + d0 + tx];
    __syncthreads();
    #pragma unroll
    for (int j = 0; j < 4; j++)
        g_KT[((size_t)bh * DH + d0 + ty + 8 * j) * LEN + p0 + tx] = tl[tx][ty + 8 * j];
}

__global__ void transpose_wo(const float* __restrict__ Wo) {
    __shared__ float tl[32][33];
    int n0 = blockIdx.y * 32, k0 = blockIdx.x * 32;
    int tx = threadIdx.x, ty = threadIdx.y;
    #pragma unroll
    for (int j = 0; j < 4; j++)
        tl[ty + 8 * j][tx] = Wo[(size_t)(n0 + ty + 8 * j) * EMB + k0 + tx];
    __syncthreads();
    #pragma unroll
    for (int j = 0; j < 4; j++)
        g_WoT[(size_t)(k0 + ty + 8 * j) * EMB + n0 + tx] = tl[tx][ty + 8 * j];
}

// ---------------------------------------------------------------------------
// Kernel 2: fused attention with tf32 mma.
// Per block: one (b,h), 32 q-rows. S tile [32 x 1024] held in smem.
// grid: (32 tiles, 64 bh) -- tiles adjacent so same-bh blocks share L2 K/V.
// ---------------------------------------------------------------------------
#define SQS  68    // == 4 mod 32
#define SKTS 136   // == 8 mod 32
#define SVS  72    // == 8 mod 32
#define SSS  1028  // == 4 mod 32

__global__ __launch_bounds__(256) void attn_mma(
    const int* __restrict__ mask, float* __restrict__ atten_out)
{
    extern __shared__ float sm[];
    float* sS  = sm;                    // 32*1028 = 32896 floats
    float* sKV = sS + 32 * SSS;         // 9216 floats (K^T chunk or V chunk)
    float* sQ  = sKV + 9216;            // 32*68 = 2176 (tf32 bits)
    float* sMk = sQ + 32 * SQS;         // 1024

    int tile = blockIdx.x, bh = blockIdx.y;
    int b = bh >> 4, h = bh & 15;
    int l0 = tile * 32;
    int tid = threadIdx.x;
    int wid = tid >> 5, lane = tid & 31;
    unsigned g = lane >> 2, t = lane & 3;

    // Stage Q tile [32 x 64] (tf32)
    #pragma unroll
    for (int e = 0; e < 2; e++) {
        int r  = (tid >> 4) + 16 * e;
        int d4 = (tid & 15) * 4;
        float4 v = *(const float4*)&g_Q[(size_t)(b * LEN + l0 + r) * EMB + h * DH + d4];
        *(uint4*)&sQ[r * SQS + d4] = *(uint4*)&(cvt4(v));
    }
    // Mask row
    #pragma unroll
    for (int e = 0; e < 4; e++) {
        int c = tid + 256 * e;
        sMk[c] = (float)mask[b * LEN + c];
    }
    __syncthreads();

    const unsigned* uQ = (const unsigned*)sQ;
    const unsigned* uKV = (const unsigned*)sKV;
    const float scale = 0.125f;

    // ---- Phase A: S = Q @ K^T (masked, scaled) ----
    for (int kt = 0; kt < 8; kt++) {
        int p0 = kt * 128;
        // Stage K^T chunk [64 d][128 pos]
        #pragma unroll
        for (int e = 0; e < 8; e++) {
            int d  = (tid >> 5) + 8 * e;
            int p4 = (tid & 31) * 4;
            float4 v = *(const float4*)&g_KT[((size_t)bh * DH + d) * LEN + p0 + p4];
            *(uint4*)&sKV[d * SKTS + p4] = cvt4(v);
        }
        __syncthreads();

        float c[2][2][4] = {};
        #pragma unroll
        for (int ks = 0; ks < 8; ks++) {
            int k0 = ks * 8;
            unsigned a[2][4];
            #pragma unroll
            for (int mi = 0; mi < 2; mi++) {
                int base = (mi * 16 + g) * SQS + k0 + t;
                a[mi][0] = uQ[base];
                a[mi][1] = uQ[base + 8 * SQS];
                a[mi][2] = uQ[base + 4];
                a[mi][3] = uQ[base + 8 * SQS + 4];
            }
            #pragma unroll
            for (int ni = 0; ni < 2; ni++) {
                int cb = wid * 16 + ni * 8 + g;
                unsigned b0 = uKV[(k0 + t) * SKTS + cb];
                unsigned b1 = uKV[(k0 + t + 4) * SKTS + cb];
                mma8(c[0][ni], a[0][0], a[0][1], a[0][2], a[0][3], b0, b1);
                mma8(c[1][ni], a[1][0], a[1][1], a[1][2], a[1][3], b0, b1);
            }
        }
        // Store S with mask + scale
        #pragma unroll
        for (int mi = 0; mi < 2; mi++) {
            int r0 = mi * 16 + g;
            #pragma unroll
            for (int ni = 0; ni < 2; ni++) {
                int col = p0 + wid * 16 + ni * 8 + 2 * t;
                float m0 = sMk[col], m1 = sMk[col + 1];
                sS[r0 * SSS + col]           = (m0 != 0.0f) ? c[mi][ni][0] * scale : MINV;
                sS[r0 * SSS + col + 1]       = (m1 != 0.0f) ? c[mi][ni][1] * scale : MINV;
                sS[(r0 + 8) * SSS + col]     = (m0 != 0.0f) ? c[mi][ni][2] * scale : MINV;
                sS[(r0 + 8) * SSS + col + 1] = (m1 != 0.0f) ? c[mi][ni][3] * scale : MINV;
            }
        }
        __syncthreads();
    }

    // ---- Phase B: softmax, write atten, store tf32 probs back ----
    for (int r = wid; r < 32; r += 8) {
        float* row = sS + r * SSS;
        float mx = -3.4e38f;
        #pragma unroll 8
        for (int cc = lane; cc < 1024; cc += 32) mx = fmaxf(mx, row[cc]);
        #pragma unroll
        for (int o = 16; o; o >>= 1) mx = fmaxf(mx, __shfl_xor_sync(0xffffffffu, mx, o));
        float sum = 0.0f;
        #pragma unroll 8
        for (int cc = lane; cc < 1024; cc += 32) {
            float e = __expf(row[cc] - mx);
            row[cc] = e;
            sum += e;
        }
        #pragma unroll
        for (int o = 16; o; o >>= 1) sum += __shfl_xor_sync(0xffffffffu, sum, o);
        float inv = 1.0f / sum;
        float* arow = atten_out + ((size_t)(b * HN + h) * LEN + (l0 + r)) * LEN;
        #pragma unroll 8
        for (int cc = lane; cc < 1024; cc += 32) {
            float p = row[cc] * inv;
            arow[cc] = p;
            row[cc] = __uint_as_float(f2tf(p));
        }
    }
    __syncthreads();

    // ---- Phase C: P @ V ----
    const unsigned* uS = (const unsigned*)sS;
    float cv[2][4] = {};
    for (int mt = 0; mt < 8; mt++) {
        int p0 = mt * 128;
        // Stage V chunk [128 pos][64 d]
        #pragma unroll
        for (int e = 0; e < 8; e++) {
            int p  = (tid >> 4) + 16 * e;
            int d4 = (tid & 15) * 4;
            float4 v = *(const float4*)&g_V[(size_t)(b * LEN + p0 + p) * EMB + h * DH + d4];
            *(uint4*)&sKV[p * SVS + d4] = cvt4(v);
        }
        __syncthreads();

        #pragma unroll
        for (int ks = 0; ks < 16; ks++) {
            int kk = ks * 8;
            unsigned a[2][4];
            #pragma unroll
            for (int mi = 0; mi < 2; mi++) {
                int base = (mi * 16 + g) * SSS + p0 + kk + t;
                a[mi][0] = uS[base];
                a[mi][1] = uS[base + 8 * SSS];
                a[mi][2] = uS[base + 4];
                a[mi][3] = uS[base + 8 * SSS + 4];
            }
            unsigned b0 = uKV[(kk + t) * SVS + wid * 8 + g];
            unsigned b1 = uKV[(kk + t + 4) * SVS + wid * 8 + g];
            mma8(cv[0], a[0][0], a[0][1], a[0][2], a[0][3], b0, b1);
            mma8(cv[1], a[1][0], a[1][1], a[1][2], a[1][3], b0, b1);
        }
        __syncthreads();
    }
    // Epilogue -> g_Val (concat layout)
    #pragma unroll
    for (int mi = 0; mi < 2; mi++) {
        int row = l0 + mi * 16 + g;
        int col = h * DH + wid * 8 + 2 * t;
        float2 v0 = make_float2(cv[mi][0], cv[mi][1]);
        float2 v1 = make_float2(cv[mi][2], cv[mi][3]);
        *(float2*)&g_Val[(size_t)(b * LEN + row) * EMB + col]     = v0;
        *(float2*)&g_Val[(size_t)(b * LEN + row + 8) * EMB + col] = v1;
    }
}

// ---------------------------------------------------------------------------
// Kernel 3: out projection.  Y = Val @ Wo^T + bo + x   (uses g_WoT row-major)
// Same structure as qkv_mma: block 128x64.
// ---------------------------------------------------------------------------
__global__ __launch_bounds__(256) void proj_mma(
    const float* __restrict__ bo, const float* __restrict__ x)
{
    __shared__ unsigned As[128 * AS_STRIDE];
    __shared__ unsigned Bs[32 * BS_STRIDE];

    int tid = threadIdx.x;
    int wid = tid >> 5, lane = tid & 31;
    int wm = wid & 3, wn = wid >> 2;
    unsigned g = lane >> 2, t = lane & 3;

    int rowbase = blockIdx.y * 128;
    int nbase   = blockIdx.x * 64;

    float acc[2][4][4] = {};

    for (int kb = 0; kb < EMB; kb += 32) {
        #pragma unroll
        for (int e = 0; e < 4; e++) {
            int r  = (tid >> 3) + 32 * e;
            int c4 = (tid & 7) * 4;
            float4 v = *(const float4*)&g_Val[(size_t)(rowbase + r) * EMB + kb + c4];
            *(uint4*)&As[r * AS_STRIDE + c4] = cvt4(v);
        }
        #pragma unroll
        for (int e = 0; e < 2; e++) {
            int k  = (tid >> 4) + 16 * e;
            int c4 = (tid & 15) * 4;
            float4 v = *(const float4*)&g_WoT[(size_t)(kb + k) * EMB + nbase + c4];
            *(uint4*)&Bs[k * BS_STRIDE + c4] = cvt4(v);
        }
        __syncthreads();

        #pragma unroll
        for (int ks = 0; ks < 4; ks++) {
            int k0 = ks * 8;
            unsigned a[2][4];
            #pragma unroll
            for (int mi = 0; mi < 2; mi++) {
                int base = (wm * 32 + mi * 16 + g) * AS_STRIDE + k0 + t;
                a[mi][0] = As[base];
                a[mi][1] = As[base + 8 * AS_STRIDE];
                a[mi][2] = As[base + 4];
                a[mi][3] = As[base + 8 * AS_STRIDE + 4];
            }
            unsigned b[4][2];
            #pragma unroll
            for (int ni = 0; ni < 4; ni++) {
                int cb = wn * 32 + ni * 8 + g;
                b[ni][0] = Bs[(k0 + t) * BS_STRIDE + cb];
                b[ni][1] = Bs[(k0 + t + 4) * BS_STRIDE + cb];
            }
            #pragma unroll
            for (int mi = 0; mi < 2; mi++)
                #pragma unroll
                for (int ni = 0; ni < 4; ni++)
                    mma8(acc[mi][ni], a[mi][0], a[mi][1], a[mi][2], a[mi][3],
                         b[ni][0], b[ni][1]);
        }
        __syncthreads();
    }

    #pragma unroll
    for (int mi = 0; mi < 2; mi++) {
        int row = rowbase + wm * 32 + mi * 16 + g;
        #pragma unroll
        for (int ni = 0; ni < 4; ni++) {
            int col = nbase + wn * 32 + ni * 8 + 2 * t;
            float b0 = bo[col], b1 = bo[col + 1];
            float2 x0 = *(const float2*)&x[(size_t)row * EMB + col];
            float2 x1 = *(const float2*)&x[(size_t)(row + 8) * EMB + col];
            float2 v0 = make_float2(acc[mi][ni][0] + b0 + x0.x, acc[mi][ni][1] + b1 + x0.y);
            float2 v1 = make_float2(acc[mi][ni][2] + b0 + x1.x, acc[mi][ni][3] + b1 + x1.y);
            *(float2*)&g_Y[(size_t)row * EMB + col]       = v0;
            *(float2*)&g_Y[(size_t)(row + 8) * EMB + col] = v1;
        }
    }
}

// ---------------------------------------------------------------------------
// Kernel 4: row LayerNorm -> d_out[:4M]
// ---------------------------------------------------------------------------
__global__ __launch_bounds__(256) void ln_kernel(
    const float* __restrict__ gamma, const float* __restrict__ beta,
    float* __restrict__ out)
{
    int r = blockIdx.x;
    const float* row = g_Y + (size_t)r * EMB;
    int tid = threadIdx.x;

    float v[4];
    float s = 0.0f, s2 = 0.0f;
    #pragma unroll
    for (int e = 0; e < 4; e++) {
        v[e] = row[tid + e * 256];
        s  += v[e];
        s2 += v[e] * v[e];
    }
    __shared__ float rs[8], rs2[8];
    #pragma unroll
    for (int o = 16; o; o >>= 1) {
        s  += __shfl_xor_sync(0xffffffffu, s,  o);
        s2 += __shfl_xor_sync(0xffffffffu, s2, o);
    }
    if ((tid & 31) == 0) { rs[tid >> 5] = s; rs2[tid >> 5] = s2; }
    __syncthreads();
    if (tid < 32) {
        float a = (tid < 8) ? rs[tid]  : 0.0f;
        float c = (tid < 8) ? rs2[tid] : 0.0f;
        #pragma unroll
        for (int o = 4; o; o >>= 1) {
            a += __shfl_xor_sync(0xffffffffu, a, o);
            c += __shfl_xor_sync(0xffffffffu, c, o);
        }
        if (tid == 0) { rs[0] = a; rs2[0] = c; }
    }
    __syncthreads();
    float mu  = rs[0] * (1.0f / 1024.0f);
    float var = rs2[0] * (1.0f / 1024.0f) - mu * mu;
    float inv = rsqrtf(var + 1e-5f);
    #pragma unroll
    for (int e = 0; e < 4; e++) {
        int c = tid + e * 256;
        out[(size_t)r * EMB + c] = (v[e] - mu) * inv * gamma[c] + beta[c];
    }
}

// ---------------------------------------------------------------------------
extern "C" void kernel_launch(void* const* d_in, const int* in_sizes, int n_in,
                              void* d_out, int out_size)
{
    const float* x     = (const float*)d_in[0];
    const int*   mask  = (const int*)  d_in[1];
    const float* Wq    = (const float*)d_in[2];
    const float* bq    = (const float*)d_in[3];
    const float* Wk    = (const float*)d_in[4];
    const float* bk    = (const float*)d_in[5];
    const float* Wv    = (const float*)d_in[6];
    const float* bv    = (const float*)d_in[7];
    const float* Wo    = (const float*)d_in[8];
    const float* bo    = (const float*)d_in[9];
    const float* gamma = (const float*)d_in[10];
    const float* beta  = (const float*)d_in[11];

    float* out   = (float*)d_out;                 // [4,1024,1024]
    float* atten = out + (size_t)BL * EMB;        // [4,16,1024,1024]

    const int ATTN_SMEM = (32 * SSS + 9216 + 32 * SQS + 1024) * (int)sizeof(float);
    cudaFuncSetAttribute(attn_mma,
                         cudaFuncAttributeMaxDynamicSharedMemorySize, ATTN_SMEM);

    transpose_wo<<<dim3(32, 32), dim3(32, 8)>>>(Wo);
    qkv_mma<<<dim3(16, 32, 3), dim3(256)>>>(x, Wq, bq, Wk, bk, Wv, bv);
    transpose_k<<<dim3(32, 2, 64), dim3(32, 8)>>>();
    attn_mma<<<dim3(32, 64), dim3(256), ATTN_SMEM>>>(mask, atten);
    proj_mma<<<dim3(16, 32), dim3(256)>>>(bo, x);
    ln_kernel<<<BL, 256>>>(gamma, beta, out);
}